// round 15
// baseline (speedup 1.0000x reference)
#include <cuda_runtime.h>
#include <cuda_bf16.h>
#include <mma.h>
#include <cstdint>

using namespace nvcuda;

// ---------------- problem constants ----------------
#define HW     4096      // 64*64
#define IMGW   64
#define BATCH  16
#define CIN    256
#define C3     768
#define CCAT   512
#define COUT   256
#define NHEAD  64
#define ATT_EPS 1e-5f

// ---------------- scratch (device globals; no allocations) ----------------
__device__ float g_qkv [(size_t)BATCH * C3   * HW];
__device__ float g_agg [(size_t)BATCH * C3   * HW];
__device__ float g_vk  [BATCH * NHEAD * 72];

// bf16 hi/lo operand mirrors (error-compensated GEMM inputs)
__device__ __nv_bfloat16 g_x_hi   [(size_t)BATCH * CIN  * HW];
__device__ __nv_bfloat16 g_x_lo   [(size_t)BATCH * CIN  * HW];
__device__ __nv_bfloat16 g_attn_hi[(size_t)BATCH * CCAT * HW];
__device__ __nv_bfloat16 g_attn_lo[(size_t)BATCH * CCAT * HW];
__device__ __nv_bfloat16 g_wqkv_hi[C3 * CIN];
__device__ __nv_bfloat16 g_wqkv_lo[C3 * CIN];
__device__ __nv_bfloat16 g_wproj_hi[COUT * CCAT];
__device__ __nv_bfloat16 g_wproj_lo[COUT * CCAT];

// ---------------- cp.async helpers ----------------
__device__ __forceinline__ void cp_async16(void* smem_dst, const void* gmem_src) {
    uint32_t s = (uint32_t)__cvta_generic_to_shared(smem_dst);
    asm volatile("cp.async.cg.shared.global [%0], [%1], 16;" :: "r"(s), "l"(gmem_src));
}
__device__ __forceinline__ void cp_commit() {
    asm volatile("cp.async.commit_group;");
}
template<int N>
__device__ __forceinline__ void cp_wait() {
    asm volatile("cp.async.wait_group %0;" :: "n"(N));
}

// ==========================================================================
// Fused fp32 -> bf16 hi/lo conversion for x, qkv_w, proj_w (one launch).
// ==========================================================================
#define N4_X   (BATCH * CIN * HW / 4)
#define N4_WQ  (C3 * CIN / 4)
#define N4_WP  (COUT * CCAT / 4)
#define BLK_X  (N4_X  / 256)
#define BLK_WQ (N4_WQ / 256)
#define BLK_WP (N4_WP / 256)

__global__ __launch_bounds__(256)
void to_hilo_all(const float4* __restrict__ x,
                 const float4* __restrict__ wq,
                 const float4* __restrict__ wp)
{
    const float4* src;
    uint2 *hi, *lo;
    int i;
    int blk = blockIdx.x;
    if (blk < BLK_X) {
        src = x;  hi = (uint2*)g_x_hi;    lo = (uint2*)g_x_lo;
        i = blk * 256 + threadIdx.x;
    } else if (blk < BLK_X + BLK_WQ) {
        src = wq; hi = (uint2*)g_wqkv_hi; lo = (uint2*)g_wqkv_lo;
        i = (blk - BLK_X) * 256 + threadIdx.x;
    } else {
        src = wp; hi = (uint2*)g_wproj_hi; lo = (uint2*)g_wproj_lo;
        i = (blk - BLK_X - BLK_WQ) * 256 + threadIdx.x;
    }
    float4 v = src[i];
    float xs[4] = {v.x, v.y, v.z, v.w};
    union { __nv_bfloat16 h[4]; uint2 u; } ph, pl;
    #pragma unroll
    for (int j = 0; j < 4; j++) {
        __nv_bfloat16 hh = __float2bfloat16_rn(xs[j]);
        ph.h[j] = hh;
        pl.h[j] = __float2bfloat16_rn(xs[j] - __bfloat162float(hh));
    }
    hi[i] = ph.u;
    lo[i] = pl.u;
}

// ==========================================================================
// bf16x3 wmma GEMM + BN + ReLU. Block 128Mx128N, BK=32, 128 threads =
// 4 warps of 64x64 (4x4 m16n16k16 frags). 2-stage cp.async, 2 CTAs/SM.
// Fragment-level software pipeline: B frags double-buffered across kk,
// A frags ping-ponged across i (reg headroom: 256/thread at this config).
// ==========================================================================
#define LDA 40
#define LDB 136
#define LDC 132

#define OFF_AHI 0
#define OFF_ALO 10240
#define OFF_BHI 20480
#define OFF_BLO 29184
#define STAGE_BYTES 37888
#define SMEM_DYN (2 * STAGE_BYTES)   // 75776 >= 128*132*4 = 67584 epilogue

template<int Mt, int Kt>
__global__ __launch_bounds__(128, 2)
void gemm_bf16x3(const __nv_bfloat16* __restrict__ Wh,
                 const __nv_bfloat16* __restrict__ Wl,
                 const __nv_bfloat16* __restrict__ Xh,
                 const __nv_bfloat16* __restrict__ Xl,
                 const float* __restrict__ scale,
                 const float* __restrict__ bias,
                 float* __restrict__ Out)
{
    extern __shared__ __align__(16) char dynsmem[];

    const int b     = blockIdx.z;
    const int mBase = blockIdx.y * 128;
    const int nBase = blockIdx.x * 128;
    const int tid   = threadIdx.x;
    const int wid   = tid >> 5;
    const int warpM = wid & 1;     // 0..1 (64 rows)
    const int warpN = wid >> 1;    // 0..1 (64 cols)

    const __nv_bfloat16* __restrict__ Xhb = Xh + (size_t)b * Kt * HW;
    const __nv_bfloat16* __restrict__ Xlb = Xl + (size_t)b * Kt * HW;

    auto stage_async = [&](int k0, char* buf) {
        __nv_bfloat16* Ahi = reinterpret_cast<__nv_bfloat16*>(buf + OFF_AHI);
        __nv_bfloat16* Alo = reinterpret_cast<__nv_bfloat16*>(buf + OFF_ALO);
        __nv_bfloat16* Bhi = reinterpret_cast<__nv_bfloat16*>(buf + OFF_BHI);
        __nv_bfloat16* Blo = reinterpret_cast<__nv_bfloat16*>(buf + OFF_BLO);
        #pragma unroll
        for (int t = 0; t < 4; t++) {
            int idx = tid + t * 128;            // 512 uint4
            int ar = idx >> 2, ac = (idx & 3) * 8;
            cp_async16(&Ahi[ar * LDA + ac], &Wh[(size_t)(mBase + ar) * Kt + k0 + ac]);
            cp_async16(&Alo[ar * LDA + ac], &Wl[(size_t)(mBase + ar) * Kt + k0 + ac]);
            int br = idx >> 4, bc = (idx & 15) * 8;
            cp_async16(&Bhi[br * LDB + bc], &Xhb[(size_t)(k0 + br) * HW + nBase + bc]);
            cp_async16(&Blo[br * LDB + bc], &Xlb[(size_t)(k0 + br) * HW + nBase + bc]);
        }
    };

    wmma::fragment<wmma::accumulator, 16, 16, 16, float> acc[4][4];
    #pragma unroll
    for (int i = 0; i < 4; i++)
        #pragma unroll
        for (int j = 0; j < 4; j++) wmma::fill_fragment(acc[i][j], 0.f);

    constexpr int NCHUNK = Kt / 32;
    stage_async(0, dynsmem);
    cp_commit();

    #pragma unroll 1
    for (int chunk = 0; chunk < NCHUNK; chunk++) {
        if (chunk + 1 < NCHUNK) {
            stage_async((chunk + 1) * 32, dynsmem + ((chunk + 1) & 1) * STAGE_BYTES);
            cp_commit();
            cp_wait<1>();
        } else {
            cp_wait<0>();
        }
        __syncthreads();

        char* buf = dynsmem + (chunk & 1) * STAGE_BYTES;
        __nv_bfloat16* Ahi = reinterpret_cast<__nv_bfloat16*>(buf + OFF_AHI);
        __nv_bfloat16* Alo = reinterpret_cast<__nv_bfloat16*>(buf + OFF_ALO);
        __nv_bfloat16* Bhi = reinterpret_cast<__nv_bfloat16*>(buf + OFF_BHI);
        __nv_bfloat16* Blo = reinterpret_cast<__nv_bfloat16*>(buf + OFF_BLO);

        // B fragments: double-buffered across the 2 kk steps
        wmma::fragment<wmma::matrix_b, 16, 16, 16, __nv_bfloat16,
                       wmma::row_major> bfh[2][4], bfl[2][4];
        #pragma unroll
        for (int j = 0; j < 4; j++) {
            const int ro = warpN * 64 + j * 16;      // kk = 0
            wmma::load_matrix_sync(bfh[0][j], &Bhi[ro], LDB);
            wmma::load_matrix_sync(bfl[0][j], &Blo[ro], LDB);
        }

        #pragma unroll
        for (int kk = 0; kk < 2; kk++) {
            if (kk == 0) {
                #pragma unroll
                for (int j = 0; j < 4; j++) {
                    const int ro = 16 * LDB + warpN * 64 + j * 16;   // kk = 1
                    wmma::load_matrix_sync(bfh[1][j], &Bhi[ro], LDB);
                    wmma::load_matrix_sync(bfl[1][j], &Blo[ro], LDB);
                }
            }
            // A fragments: ping-pong across i
            wmma::fragment<wmma::matrix_a, 16, 16, 16, __nv_bfloat16,
                           wmma::row_major> afh[2], afl[2];
            {
                const int ro = (warpM * 64) * LDA + kk * 16;
                wmma::load_matrix_sync(afh[0], &Ahi[ro], LDA);
                wmma::load_matrix_sync(afl[0], &Alo[ro], LDA);
            }
            #pragma unroll
            for (int i = 0; i < 4; i++) {
                if (i < 3) {
                    const int ro = (warpM * 64 + (i + 1) * 16) * LDA + kk * 16;
                    wmma::load_matrix_sync(afh[(i + 1) & 1], &Ahi[ro], LDA);
                    wmma::load_matrix_sync(afl[(i + 1) & 1], &Alo[ro], LDA);
                }
                #pragma unroll
                for (int j = 0; j < 4; j++) {
                    wmma::mma_sync(acc[i][j], afl[i & 1], bfh[kk][j], acc[i][j]);
                    wmma::mma_sync(acc[i][j], afh[i & 1], bfl[kk][j], acc[i][j]);
                    wmma::mma_sync(acc[i][j], afh[i & 1], bfh[kk][j], acc[i][j]);
                }
            }
        }
        __syncthreads();
    }

    // ---- single-pass epilogue: Cs[128][LDC] = 67.6KB fits dynsmem, BN+ReLU
    float* Cs = reinterpret_cast<float*>(dynsmem);
    #pragma unroll
    for (int i = 0; i < 4; i++)
        #pragma unroll
        for (int j = 0; j < 4; j++)
            wmma::store_matrix_sync(
                &Cs[(warpM * 64 + i * 16) * LDC + warpN * 64 + j * 16],
                acc[i][j], LDC, wmma::mem_row_major);
    __syncthreads();
    #pragma unroll
    for (int t = 0; t < 32; t++) {
        int idx = tid + t * 128;              // 4096 float4
        int r = idx >> 5, c4 = (idx & 31) * 4;
        int m = mBase + r;
        const float sc = scale[m], bi = bias[m];
        float4 v = *reinterpret_cast<const float4*>(&Cs[r * LDC + c4]);
        v.x = fmaxf(fmaf(v.x, sc, bi), 0.f);
        v.y = fmaxf(fmaf(v.y, sc, bi), 0.f);
        v.z = fmaxf(fmaf(v.z, sc, bi), 0.f);
        v.w = fmaxf(fmaf(v.w, sc, bi), 0.f);
        *reinterpret_cast<float4*>(
            &Out[(size_t)b * Mt * HW + (size_t)m * HW + nBase + c4]) = v;
    }
}

// ==========================================================================
// Fused depthwise 5x5 + per-channel 1x1, smem-tiled with sliding window.
// ==========================================================================
#define TILE_W 68
__global__ __launch_bounds__(256)
void dw5x5_pw_kernel(const float* __restrict__ dw_w,
                     const float* __restrict__ dw_b,
                     const float* __restrict__ pw_w,
                     const float* __restrict__ pw_b)
{
    __shared__ float tile[TILE_W * TILE_W];
    const int c = blockIdx.x;
    const int b = blockIdx.y;
    const int tid = threadIdx.x;

    const float* __restrict__ src = g_qkv + ((size_t)b * C3 + c) * HW;

    for (int idx = tid; idx < TILE_W * TILE_W; idx += 256) {
        int r = idx / TILE_W - 2;
        int cc = idx % TILE_W - 2;
        float v = 0.f;
        if ((unsigned)r < IMGW && (unsigned)cc < IMGW) v = src[r * IMGW + cc];
        tile[idx] = v;
    }

    float wreg[25];
    #pragma unroll
    for (int i = 0; i < 25; i++) wreg[i] = __ldg(&dw_w[c * 25 + i]);
    const float dwb = __ldg(&dw_b[c]);
    const float pww = __ldg(&pw_w[c]);
    const float pwb = __ldg(&pw_b[c]);
    __syncthreads();

    const int row = tid >> 2;
    const int xs  = (tid & 3) * 16;

    float acc[16];
    #pragma unroll
    for (int i = 0; i < 16; i++) acc[i] = 0.f;

    #pragma unroll
    for (int dy = 0; dy < 5; dy++) {
        const float* trow = &tile[(row + dy) * TILE_W + xs];
        float win[20];
        #pragma unroll
        for (int i = 0; i < 20; i++) win[i] = trow[i];
        const float w0 = wreg[dy * 5 + 0], w1 = wreg[dy * 5 + 1],
                    w2 = wreg[dy * 5 + 2], w3 = wreg[dy * 5 + 3],
                    w4 = wreg[dy * 5 + 4];
        #pragma unroll
        for (int i = 0; i < 16; i++) {
            float s = acc[i];
            s = fmaf(win[i + 0], w0, s);
            s = fmaf(win[i + 1], w1, s);
            s = fmaf(win[i + 2], w2, s);
            s = fmaf(win[i + 3], w3, s);
            s = fmaf(win[i + 4], w4, s);
            acc[i] = s;
        }
    }

    float* dst = g_agg + ((size_t)b * C3 + c) * HW + row * IMGW + xs;
    #pragma unroll
    for (int i4 = 0; i4 < 16; i4 += 4) {
        float4 v;
        v.x = fmaf(acc[i4 + 0] + dwb, pww, pwb);
        v.y = fmaf(acc[i4 + 1] + dwb, pww, pwb);
        v.z = fmaf(acc[i4 + 2] + dwb, pww, pwb);
        v.w = fmaf(acc[i4 + 3] + dwb, pww, pwb);
        *reinterpret_cast<float4*>(dst + i4) = v;
    }
}

// ==========================================================================
// Attention phase 1: smem-staged warp-per-d with cp.async double buffer.
// ==========================================================================
#define RCHUNK 512
#define RBUF_FLOATS (16 * RCHUNK)
#define RSMEM_DYN (2 * RBUF_FLOATS * 4)    // 65536 bytes

__global__ __launch_bounds__(256)
void attn_reduce_kernel()
{
    extern __shared__ __align__(16) float rsm[];

    const int head = blockIdx.x;
    const int b    = blockIdx.y;
    const float* __restrict__ src = (head < 32) ? g_qkv : g_agg;
    const int ch0 = (head & 31) * 24;
    const float* __restrict__ base = src + ((size_t)b * C3 + ch0) * HW;

    const int tid  = threadIdx.x;
    const int wid  = tid >> 5;
    const int lane = tid & 31;

    auto stage = [&](int n0, float* buf) {
        #pragma unroll
        for (int t = 0; t < 4; t++) {
            int idx = tid + t * 256;
            int ch  = idx >> 7;
            int pos = (idx & 127) * 4;
            cp_async16(&buf[ch * RCHUNK + pos],
                       &base[(size_t)(8 + ch) * HW + n0 + pos]);
            cp_async16(&buf[8 * RCHUNK + ch * RCHUNK + pos],
                       &base[(size_t)(16 + ch) * HW + n0 + pos]);
        }
    };

    float acc[8];
    #pragma unroll
    for (int e = 0; e < 8; e++) acc[e] = 0.f;
    float ksum[8];
    #pragma unroll
    for (int e = 0; e < 8; e++) ksum[e] = 0.f;

    constexpr int NCH = HW / RCHUNK;
    stage(0, rsm);
    cp_commit();

    #pragma unroll 1
    for (int c = 0; c < NCH; c++) {
        if (c + 1 < NCH) {
            stage((c + 1) * RCHUNK, rsm + ((c + 1) & 1) * RBUF_FLOATS);
            cp_commit();
            cp_wait<1>();
        } else {
            cp_wait<0>();
        }
        __syncthreads();

        const float* ks = rsm + (c & 1) * RBUF_FLOATS;
        const float* vs = ks + 8 * RCHUNK;

        if (wid == 0) {
            #pragma unroll
            for (int i = 0; i < RCHUNK / 32; i++) {
                const int n = lane + 32 * i;
                const float vd = vs[0 * RCHUNK + n];
                #pragma unroll
                for (int e = 0; e < 8; e++) {
                    const float kv = fmaxf(ks[e * RCHUNK + n], 0.f);
                    acc[e]  = fmaf(vd, kv, acc[e]);
                    ksum[e] += kv;
                }
            }
        } else {
            #pragma unroll
            for (int i = 0; i < RCHUNK / 32; i++) {
                const int n = lane + 32 * i;
                const float vd = vs[wid * RCHUNK + n];
                #pragma unroll
                for (int e = 0; e < 8; e++)
                    acc[e] = fmaf(vd, fmaxf(ks[e * RCHUNK + n], 0.f), acc[e]);
            }
        }
        __syncthreads();
    }

    float* dst = &g_vk[((size_t)b * NHEAD + head) * 72];
    #pragma unroll
    for (int e = 0; e < 8; e++) {
        float v = acc[e];
        #pragma unroll
        for (int off = 16; off > 0; off >>= 1)
            v += __shfl_down_sync(0xffffffffu, v, off);
        if (lane == 0) dst[wid * 8 + e] = v;
    }
    if (wid == 0) {
        #pragma unroll
        for (int e = 0; e < 8; e++) {
            float v = ksum[e];
            #pragma unroll
            for (int off = 16; off > 0; off >>= 1)
                v += __shfl_down_sync(0xffffffffu, v, off);
            if (lane == 0) dst[64 + e] = v;
        }
    }
}

// ==========================================================================
// Attention phase 2: apply + normalize; float4 vectorized, packed bf16 out.
// ==========================================================================
__global__ __launch_bounds__(256)
void attn_apply_kernel()
{
    const int head = blockIdx.y;
    const int b    = blockIdx.z;
    const int n    = (blockIdx.x * 256 + threadIdx.x) * 4;

    __shared__ float s[72];
    if (threadIdx.x < 72)
        s[threadIdx.x] = g_vk[((size_t)b * NHEAD + head) * 72 + threadIdx.x];
    __syncthreads();

    const float* __restrict__ src = (head < 32) ? g_qkv : g_agg;
    const int ch0 = (head & 31) * 24;
    const float* __restrict__ base = src + ((size_t)b * C3 + ch0) * HW;

    float4 q[8];
    #pragma unroll
    for (int e = 0; e < 8; e++) {
        float4 t = *reinterpret_cast<const float4*>(&base[(size_t)e * HW + n]);
        q[e].x = fmaxf(t.x, 0.f); q[e].y = fmaxf(t.y, 0.f);
        q[e].z = fmaxf(t.z, 0.f); q[e].w = fmaxf(t.w, 0.f);
    }

    float4 denom = make_float4(ATT_EPS, ATT_EPS, ATT_EPS, ATT_EPS);
    #pragma unroll
    for (int e = 0; e < 8; e++) {
        const float ks = s[64 + e];
        denom.x = fmaf(ks, q[e].x, denom.x);
        denom.y = fmaf(ks, q[e].y, denom.y);
        denom.z = fmaf(ks, q[e].z, denom.z);
        denom.w = fmaf(ks, q[e].w, denom.w);
    }
    const float4 inv = make_float4(1.f / denom.x, 1.f / denom.y,
                                   1.f / denom.z, 1.f / denom.w);

    const size_t obase = ((size_t)b * CCAT + head * 8) * HW + n;
    #pragma unroll
    for (int d = 0; d < 8; d++) {
        float4 o = make_float4(0.f, 0.f, 0.f, 0.f);
        #pragma unroll
        for (int e = 0; e < 8; e++) {
            const float vk = s[d * 8 + e];
            o.x = fmaf(vk, q[e].x, o.x);
            o.y = fmaf(vk, q[e].y, o.y);
            o.z = fmaf(vk, q[e].z, o.z);
            o.w = fmaf(vk, q[e].w, o.w);
        }
        float vals[4] = {o.x * inv.x, o.y * inv.y, o.z * inv.z, o.w * inv.w};
        union { __nv_bfloat16 h[4]; uint2 u; } ph, pl;
        #pragma unroll
        for (int j = 0; j < 4; j++) {
            __nv_bfloat16 hh = __float2bfloat16_rn(vals[j]);
            ph.h[j] = hh;
            pl.h[j] = __float2bfloat16_rn(vals[j] - __bfloat162float(hh));
        }
        *reinterpret_cast<uint2*>(&g_attn_hi[obase + (size_t)d * HW]) = ph.u;
        *reinterpret_cast<uint2*>(&g_attn_lo[obase + (size_t)d * HW]) = pl.u;
    }
}

// ==========================================================================
// launcher
// ==========================================================================
extern "C" void kernel_launch(void* const* d_in, const int* in_sizes, int n_in,
                              void* d_out, int out_size)
{
    const float* x            = (const float*)d_in[0];
    const float* qkv_w        = (const float*)d_in[1];
    const float* qkv_bn_scale = (const float*)d_in[2];
    const float* qkv_bn_bias  = (const float*)d_in[3];
    const float* agg_dw_w     = (const float*)d_in[4];
    const float* agg_dw_b     = (const float*)d_in[5];
    const float* agg_pw_w     = (const float*)d_in[6];
    const float* agg_pw_b     = (const float*)d_in[7];
    const float* proj_w       = (const float*)d_in[8];
    const float* proj_bn_scale= (const float*)d_in[9];
    const float* proj_bn_bias = (const float*)d_in[10];
    float* out = (float*)d_out;

    __nv_bfloat16 *xh, *xl, *wqh, *wql, *wph, *wpl, *ah, *al;
    cudaGetSymbolAddress((void**)&xh,  g_x_hi);
    cudaGetSymbolAddress((void**)&xl,  g_x_lo);
    cudaGetSymbolAddress((void**)&wqh, g_wqkv_hi);
    cudaGetSymbolAddress((void**)&wql, g_wqkv_lo);
    cudaGetSymbolAddress((void**)&wph, g_wproj_hi);
    cudaGetSymbolAddress((void**)&wpl, g_wproj_lo);
    cudaGetSymbolAddress((void**)&ah,  g_attn_hi);
    cudaGetSymbolAddress((void**)&al,  g_attn_lo);

    (void)cudaFuncSetAttribute(gemm_bf16x3<C3, CIN>,
                               cudaFuncAttributeMaxDynamicSharedMemorySize, SMEM_DYN);
    (void)cudaFuncSetAttribute(gemm_bf16x3<COUT, CCAT>,
                               cudaFuncAttributeMaxDynamicSharedMemorySize, SMEM_DYN);
    (void)cudaFuncSetAttribute(attn_reduce_kernel,
                               cudaFuncAttributeMaxDynamicSharedMemorySize, RSMEM_DYN);

    // 0) fused pre-split of all operands to bf16 hi/lo (one launch)
    {
        to_hilo_all<<<BLK_X + BLK_WQ + BLK_WP, 256>>>(
            (const float4*)x, (const float4*)qkv_w, (const float4*)proj_w);
    }
    // 1) qkv = relu(bn(conv1x1(x)))
    {
        float* gq;
        cudaGetSymbolAddress((void**)&gq, g_qkv);
        dim3 grid(HW / 128, C3 / 128, BATCH);
        gemm_bf16x3<C3, CIN><<<grid, 128, SMEM_DYN>>>(
            wqh, wql, xh, xl, qkv_bn_scale, qkv_bn_bias, gq);
    }
    // 2) agg = pw(dw5x5(qkv))
    {
        dim3 grid(C3, BATCH);
        dw5x5_pw_kernel<<<grid, 256>>>(agg_dw_w, agg_dw_b, agg_pw_w, agg_pw_b);
    }
    // 3a) per-head vk / ksum
    {
        dim3 grid(NHEAD, BATCH);
        attn_reduce_kernel<<<grid, 256, RSMEM_DYN>>>();
    }
    // 3b) apply + normalize (emits bf16 hi/lo)
    {
        dim3 grid(HW / 1024, NHEAD, BATCH);
        attn_apply_kernel<<<grid, 256>>>();
    }
    // 4) out = relu(bn(conv1x1(attn)))
    {
        dim3 grid(HW / 128, COUT / 128, BATCH);
        gemm_bf16x3<COUT, CCAT><<<grid, 128, SMEM_DYN>>>(
            wph, wpl, ah, al, proj_bn_scale, proj_bn_bias, out);
    }
}

// round 16
// speedup vs baseline: 1.4375x; 1.4375x over previous
#include <cuda_runtime.h>
#include <cuda_bf16.h>
#include <mma.h>
#include <cstdint>

using namespace nvcuda;

// ---------------- problem constants ----------------
#define HW     4096      // 64*64
#define IMGW   64
#define BATCH  16
#define CIN    256
#define C3     768
#define CCAT   512
#define COUT   256
#define NHEAD  64
#define ATT_EPS 1e-5f

// ---------------- scratch (device globals; no allocations) ----------------
__device__ float g_qkv [(size_t)BATCH * C3   * HW];
__device__ float g_agg [(size_t)BATCH * C3   * HW];
__device__ float g_vk  [BATCH * NHEAD * 72];

// bf16 hi/lo operand mirrors (error-compensated GEMM inputs)
__device__ __nv_bfloat16 g_x_hi   [(size_t)BATCH * CIN  * HW];
__device__ __nv_bfloat16 g_x_lo   [(size_t)BATCH * CIN  * HW];
__device__ __nv_bfloat16 g_attn_hi[(size_t)BATCH * CCAT * HW];
__device__ __nv_bfloat16 g_attn_lo[(size_t)BATCH * CCAT * HW];
__device__ __nv_bfloat16 g_wqkv_hi[C3 * CIN];
__device__ __nv_bfloat16 g_wqkv_lo[C3 * CIN];
__device__ __nv_bfloat16 g_wproj_hi[COUT * CCAT];
__device__ __nv_bfloat16 g_wproj_lo[COUT * CCAT];

// ---------------- cp.async helpers ----------------
__device__ __forceinline__ void cp_async16(void* smem_dst, const void* gmem_src) {
    uint32_t s = (uint32_t)__cvta_generic_to_shared(smem_dst);
    asm volatile("cp.async.cg.shared.global [%0], [%1], 16;" :: "r"(s), "l"(gmem_src));
}
__device__ __forceinline__ void cp_commit() {
    asm volatile("cp.async.commit_group;");
}
template<int N>
__device__ __forceinline__ void cp_wait() {
    asm volatile("cp.async.wait_group %0;" :: "n"(N));
}

// ==========================================================================
// Fused fp32 -> bf16 hi/lo conversion for x, qkv_w, proj_w (one launch).
// ==========================================================================
#define N4_X   (BATCH * CIN * HW / 4)
#define N4_WQ  (C3 * CIN / 4)
#define N4_WP  (COUT * CCAT / 4)
#define BLK_X  (N4_X  / 256)
#define BLK_WQ (N4_WQ / 256)
#define BLK_WP (N4_WP / 256)

__global__ __launch_bounds__(256)
void to_hilo_all(const float4* __restrict__ x,
                 const float4* __restrict__ wq,
                 const float4* __restrict__ wp)
{
    const float4* src;
    uint2 *hi, *lo;
    int i;
    int blk = blockIdx.x;
    if (blk < BLK_X) {
        src = x;  hi = (uint2*)g_x_hi;    lo = (uint2*)g_x_lo;
        i = blk * 256 + threadIdx.x;
    } else if (blk < BLK_X + BLK_WQ) {
        src = wq; hi = (uint2*)g_wqkv_hi; lo = (uint2*)g_wqkv_lo;
        i = (blk - BLK_X) * 256 + threadIdx.x;
    } else {
        src = wp; hi = (uint2*)g_wproj_hi; lo = (uint2*)g_wproj_lo;
        i = (blk - BLK_X - BLK_WQ) * 256 + threadIdx.x;
    }
    float4 v = src[i];
    float xs[4] = {v.x, v.y, v.z, v.w};
    union { __nv_bfloat16 h[4]; uint2 u; } ph, pl;
    #pragma unroll
    for (int j = 0; j < 4; j++) {
        __nv_bfloat16 hh = __float2bfloat16_rn(xs[j]);
        ph.h[j] = hh;
        pl.h[j] = __float2bfloat16_rn(xs[j] - __bfloat162float(hh));
    }
    hi[i] = ph.u;
    lo[i] = pl.u;
}

// ==========================================================================
// bf16x3 wmma GEMM + BN + ReLU. Block 128Mx128N, BK=32, 128 threads =
// 4 warps of 64x64 (4x4 m16n16k16 frags). 2-stage cp.async, 2 CTAs/SM.
//   Out[b,m,n] = relu(scale[m] * sum_k W[m,k] X[b,k,n] + bias[m])
// ==========================================================================
#define LDA 40
#define LDB 136
#define LDC 132

#define OFF_AHI 0
#define OFF_ALO 10240
#define OFF_BHI 20480
#define OFF_BLO 29184
#define STAGE_BYTES 37888
#define SMEM_DYN (2 * STAGE_BYTES)   // 75776 >= 128*132*4 = 67584 epilogue

template<int Mt, int Kt>
__global__ __launch_bounds__(128, 2)
void gemm_bf16x3(const __nv_bfloat16* __restrict__ Wh,
                 const __nv_bfloat16* __restrict__ Wl,
                 const __nv_bfloat16* __restrict__ Xh,
                 const __nv_bfloat16* __restrict__ Xl,
                 const float* __restrict__ scale,
                 const float* __restrict__ bias,
                 float* __restrict__ Out)
{
    extern __shared__ __align__(16) char dynsmem[];

    const int b     = blockIdx.z;
    const int mBase = blockIdx.y * 128;
    const int nBase = blockIdx.x * 128;
    const int tid   = threadIdx.x;
    const int wid   = tid >> 5;
    const int warpM = wid & 1;     // 0..1 (64 rows)
    const int warpN = wid >> 1;    // 0..1 (64 cols)

    const __nv_bfloat16* __restrict__ Xhb = Xh + (size_t)b * Kt * HW;
    const __nv_bfloat16* __restrict__ Xlb = Xl + (size_t)b * Kt * HW;

    auto stage_async = [&](int k0, char* buf) {
        __nv_bfloat16* Ahi = reinterpret_cast<__nv_bfloat16*>(buf + OFF_AHI);
        __nv_bfloat16* Alo = reinterpret_cast<__nv_bfloat16*>(buf + OFF_ALO);
        __nv_bfloat16* Bhi = reinterpret_cast<__nv_bfloat16*>(buf + OFF_BHI);
        __nv_bfloat16* Blo = reinterpret_cast<__nv_bfloat16*>(buf + OFF_BLO);
        #pragma unroll
        for (int t = 0; t < 4; t++) {
            int idx = tid + t * 128;            // 512 uint4
            int ar = idx >> 2, ac = (idx & 3) * 8;
            cp_async16(&Ahi[ar * LDA + ac], &Wh[(size_t)(mBase + ar) * Kt + k0 + ac]);
            cp_async16(&Alo[ar * LDA + ac], &Wl[(size_t)(mBase + ar) * Kt + k0 + ac]);
            int br = idx >> 4, bc = (idx & 15) * 8;
            cp_async16(&Bhi[br * LDB + bc], &Xhb[(size_t)(k0 + br) * HW + nBase + bc]);
            cp_async16(&Blo[br * LDB + bc], &Xlb[(size_t)(k0 + br) * HW + nBase + bc]);
        }
    };

    wmma::fragment<wmma::accumulator, 16, 16, 16, float> acc[4][4];
    #pragma unroll
    for (int i = 0; i < 4; i++)
        #pragma unroll
        for (int j = 0; j < 4; j++) wmma::fill_fragment(acc[i][j], 0.f);

    constexpr int NCHUNK = Kt / 32;
    stage_async(0, dynsmem);
    cp_commit();

    #pragma unroll 1
    for (int chunk = 0; chunk < NCHUNK; chunk++) {
        if (chunk + 1 < NCHUNK) {
            stage_async((chunk + 1) * 32, dynsmem + ((chunk + 1) & 1) * STAGE_BYTES);
            cp_commit();
            cp_wait<1>();
        } else {
            cp_wait<0>();
        }
        __syncthreads();

        char* buf = dynsmem + (chunk & 1) * STAGE_BYTES;
        __nv_bfloat16* Ahi = reinterpret_cast<__nv_bfloat16*>(buf + OFF_AHI);
        __nv_bfloat16* Alo = reinterpret_cast<__nv_bfloat16*>(buf + OFF_ALO);
        __nv_bfloat16* Bhi = reinterpret_cast<__nv_bfloat16*>(buf + OFF_BHI);
        __nv_bfloat16* Blo = reinterpret_cast<__nv_bfloat16*>(buf + OFF_BLO);

        #pragma unroll
        for (int kk = 0; kk < 2; kk++) {
            wmma::fragment<wmma::matrix_b, 16, 16, 16, __nv_bfloat16,
                           wmma::row_major> bfh[4], bfl[4];
            #pragma unroll
            for (int j = 0; j < 4; j++) {
                const int ro = (kk * 16) * LDB + warpN * 64 + j * 16;
                wmma::load_matrix_sync(bfh[j], &Bhi[ro], LDB);
                wmma::load_matrix_sync(bfl[j], &Blo[ro], LDB);
            }
            #pragma unroll
            for (int i = 0; i < 4; i++) {
                wmma::fragment<wmma::matrix_a, 16, 16, 16, __nv_bfloat16,
                               wmma::row_major> afh, afl;
                const int ro = (warpM * 64 + i * 16) * LDA + kk * 16;
                wmma::load_matrix_sync(afh, &Ahi[ro], LDA);
                wmma::load_matrix_sync(afl, &Alo[ro], LDA);
                #pragma unroll
                for (int j = 0; j < 4; j++) {
                    wmma::mma_sync(acc[i][j], afl, bfh[j], acc[i][j]);
                    wmma::mma_sync(acc[i][j], afh, bfl[j], acc[i][j]);
                    wmma::mma_sync(acc[i][j], afh, bfh[j], acc[i][j]);
                }
            }
        }
        __syncthreads();
    }

    // ---- single-pass epilogue: Cs[128][LDC] = 67.6KB fits dynsmem, BN+ReLU
    float* Cs = reinterpret_cast<float*>(dynsmem);
    #pragma unroll
    for (int i = 0; i < 4; i++)
        #pragma unroll
        for (int j = 0; j < 4; j++)
            wmma::store_matrix_sync(
                &Cs[(warpM * 64 + i * 16) * LDC + warpN * 64 + j * 16],
                acc[i][j], LDC, wmma::mem_row_major);
    __syncthreads();
    #pragma unroll
    for (int t = 0; t < 32; t++) {
        int idx = tid + t * 128;              // 4096 float4
        int r = idx >> 5, c4 = (idx & 31) * 4;
        int m = mBase + r;
        const float sc = scale[m], bi = bias[m];
        float4 v = *reinterpret_cast<const float4*>(&Cs[r * LDC + c4]);
        v.x = fmaxf(fmaf(v.x, sc, bi), 0.f);
        v.y = fmaxf(fmaf(v.y, sc, bi), 0.f);
        v.z = fmaxf(fmaf(v.z, sc, bi), 0.f);
        v.w = fmaxf(fmaf(v.w, sc, bi), 0.f);
        *reinterpret_cast<float4*>(
            &Out[(size_t)b * Mt * HW + (size_t)m * HW + nBase + c4]) = v;
    }
}

// ==========================================================================
// Fused depthwise 5x5 + per-channel 1x1, smem-tiled with sliding window.
// ==========================================================================
#define TILE_W 68
__global__ __launch_bounds__(256)
void dw5x5_pw_kernel(const float* __restrict__ dw_w,
                     const float* __restrict__ dw_b,
                     const float* __restrict__ pw_w,
                     const float* __restrict__ pw_b)
{
    __shared__ float tile[TILE_W * TILE_W];
    const int c = blockIdx.x;
    const int b = blockIdx.y;
    const int tid = threadIdx.x;

    const float* __restrict__ src = g_qkv + ((size_t)b * C3 + c) * HW;

    for (int idx = tid; idx < TILE_W * TILE_W; idx += 256) {
        int r = idx / TILE_W - 2;
        int cc = idx % TILE_W - 2;
        float v = 0.f;
        if ((unsigned)r < IMGW && (unsigned)cc < IMGW) v = src[r * IMGW + cc];
        tile[idx] = v;
    }

    float wreg[25];
    #pragma unroll
    for (int i = 0; i < 25; i++) wreg[i] = __ldg(&dw_w[c * 25 + i]);
    const float dwb = __ldg(&dw_b[c]);
    const float pww = __ldg(&pw_w[c]);
    const float pwb = __ldg(&pw_b[c]);
    __syncthreads();

    const int row = tid >> 2;
    const int xs  = (tid & 3) * 16;

    float acc[16];
    #pragma unroll
    for (int i = 0; i < 16; i++) acc[i] = 0.f;

    #pragma unroll
    for (int dy = 0; dy < 5; dy++) {
        const float* trow = &tile[(row + dy) * TILE_W + xs];
        float win[20];
        #pragma unroll
        for (int i = 0; i < 20; i++) win[i] = trow[i];
        const float w0 = wreg[dy * 5 + 0], w1 = wreg[dy * 5 + 1],
                    w2 = wreg[dy * 5 + 2], w3 = wreg[dy * 5 + 3],
                    w4 = wreg[dy * 5 + 4];
        #pragma unroll
        for (int i = 0; i < 16; i++) {
            float s = acc[i];
            s = fmaf(win[i + 0], w0, s);
            s = fmaf(win[i + 1], w1, s);
            s = fmaf(win[i + 2], w2, s);
            s = fmaf(win[i + 3], w3, s);
            s = fmaf(win[i + 4], w4, s);
            acc[i] = s;
        }
    }

    float* dst = g_agg + ((size_t)b * C3 + c) * HW + row * IMGW + xs;
    #pragma unroll
    for (int i4 = 0; i4 < 16; i4 += 4) {
        float4 v;
        v.x = fmaf(acc[i4 + 0] + dwb, pww, pwb);
        v.y = fmaf(acc[i4 + 1] + dwb, pww, pwb);
        v.z = fmaf(acc[i4 + 2] + dwb, pww, pwb);
        v.w = fmaf(acc[i4 + 3] + dwb, pww, pwb);
        *reinterpret_cast<float4*>(dst + i4) = v;
    }
}

// ==========================================================================
// Attention phase 1: smem-staged warp-per-d with cp.async double buffer.
// ReLU applied at consumption (cp.async is a raw copy).
// ==========================================================================
#define RCHUNK 512
#define RBUF_FLOATS (16 * RCHUNK)          // ks(8ch) + vs(8ch) per buffer
#define RSMEM_DYN (2 * RBUF_FLOATS * 4)    // 65536 bytes

__global__ __launch_bounds__(256)
void attn_reduce_kernel()
{
    extern __shared__ __align__(16) float rsm[];

    const int head = blockIdx.x;
    const int b    = blockIdx.y;
    const float* __restrict__ src = (head < 32) ? g_qkv : g_agg;
    const int ch0 = (head & 31) * 24;
    const float* __restrict__ base = src + ((size_t)b * C3 + ch0) * HW;

    const int tid  = threadIdx.x;
    const int wid  = tid >> 5;
    const int lane = tid & 31;

    auto stage = [&](int n0, float* buf) {
        #pragma unroll
        for (int t = 0; t < 4; t++) {
            int idx = tid + t * 256;           // 0..1023
            int ch  = idx >> 7;                // 0..7
            int pos = (idx & 127) * 4;
            cp_async16(&buf[ch * RCHUNK + pos],
                       &base[(size_t)(8 + ch) * HW + n0 + pos]);
            cp_async16(&buf[8 * RCHUNK + ch * RCHUNK + pos],
                       &base[(size_t)(16 + ch) * HW + n0 + pos]);
        }
    };

    float acc[8];
    #pragma unroll
    for (int e = 0; e < 8; e++) acc[e] = 0.f;
    float ksum[8];
    #pragma unroll
    for (int e = 0; e < 8; e++) ksum[e] = 0.f;

    constexpr int NCH = HW / RCHUNK;
    stage(0, rsm);
    cp_commit();

    #pragma unroll 1
    for (int c = 0; c < NCH; c++) {
        if (c + 1 < NCH) {
            stage((c + 1) * RCHUNK, rsm + ((c + 1) & 1) * RBUF_FLOATS);
            cp_commit();
            cp_wait<1>();
        } else {
            cp_wait<0>();
        }
        __syncthreads();

        const float* ks = rsm + (c & 1) * RBUF_FLOATS;
        const float* vs = ks + 8 * RCHUNK;

        if (wid == 0) {
            #pragma unroll
            for (int i = 0; i < RCHUNK / 32; i++) {
                const int n = lane + 32 * i;
                const float vd = vs[0 * RCHUNK + n];
                #pragma unroll
                for (int e = 0; e < 8; e++) {
                    const float kv = fmaxf(ks[e * RCHUNK + n], 0.f);
                    acc[e]  = fmaf(vd, kv, acc[e]);
                    ksum[e] += kv;
                }
            }
        } else {
            #pragma unroll
            for (int i = 0; i < RCHUNK / 32; i++) {
                const int n = lane + 32 * i;
                const float vd = vs[wid * RCHUNK + n];
                #pragma unroll
                for (int e = 0; e < 8; e++)
                    acc[e] = fmaf(vd, fmaxf(ks[e * RCHUNK + n], 0.f), acc[e]);
            }
        }
        __syncthreads();
    }

    float* dst = &g_vk[((size_t)b * NHEAD + head) * 72];
    #pragma unroll
    for (int e = 0; e < 8; e++) {
        float v = acc[e];
        #pragma unroll
        for (int off = 16; off > 0; off >>= 1)
            v += __shfl_down_sync(0xffffffffu, v, off);
        if (lane == 0) dst[wid * 8 + e] = v;
    }
    if (wid == 0) {
        #pragma unroll
        for (int e = 0; e < 8; e++) {
            float v = ksum[e];
            #pragma unroll
            for (int off = 16; off > 0; off >>= 1)
                v += __shfl_down_sync(0xffffffffu, v, off);
            if (lane == 0) dst[64 + e] = v;
        }
    }
}

// ==========================================================================
// Attention phase 2: apply + normalize; float4 vectorized, packed bf16 out.
// ==========================================================================
__global__ __launch_bounds__(256)
void attn_apply_kernel()
{
    const int head = blockIdx.y;
    const int b    = blockIdx.z;
    const int n    = (blockIdx.x * 256 + threadIdx.x) * 4;

    __shared__ float s[72];
    if (threadIdx.x < 72)
        s[threadIdx.x] = g_vk[((size_t)b * NHEAD + head) * 72 + threadIdx.x];
    __syncthreads();

    const float* __restrict__ src = (head < 32) ? g_qkv : g_agg;
    const int ch0 = (head & 31) * 24;
    const float* __restrict__ base = src + ((size_t)b * C3 + ch0) * HW;

    float4 q[8];
    #pragma unroll
    for (int e = 0; e < 8; e++) {
        float4 t = *reinterpret_cast<const float4*>(&base[(size_t)e * HW + n]);
        q[e].x = fmaxf(t.x, 0.f); q[e].y = fmaxf(t.y, 0.f);
        q[e].z = fmaxf(t.z, 0.f); q[e].w = fmaxf(t.w, 0.f);
    }

    float4 denom = make_float4(ATT_EPS, ATT_EPS, ATT_EPS, ATT_EPS);
    #pragma unroll
    for (int e = 0; e < 8; e++) {
        const float ks = s[64 + e];
        denom.x = fmaf(ks, q[e].x, denom.x);
        denom.y = fmaf(ks, q[e].y, denom.y);
        denom.z = fmaf(ks, q[e].z, denom.z);
        denom.w = fmaf(ks, q[e].w, denom.w);
    }
    const float4 inv = make_float4(1.f / denom.x, 1.f / denom.y,
                                   1.f / denom.z, 1.f / denom.w);

    const size_t obase = ((size_t)b * CCAT + head * 8) * HW + n;
    #pragma unroll
    for (int d = 0; d < 8; d++) {
        float4 o = make_float4(0.f, 0.f, 0.f, 0.f);
        #pragma unroll
        for (int e = 0; e < 8; e++) {
            const float vk = s[d * 8 + e];
            o.x = fmaf(vk, q[e].x, o.x);
            o.y = fmaf(vk, q[e].y, o.y);
            o.z = fmaf(vk, q[e].z, o.z);
            o.w = fmaf(vk, q[e].w, o.w);
        }
        float vals[4] = {o.x * inv.x, o.y * inv.y, o.z * inv.z, o.w * inv.w};
        union { __nv_bfloat16 h[4]; uint2 u; } ph, pl;
        #pragma unroll
        for (int j = 0; j < 4; j++) {
            __nv_bfloat16 hh = __float2bfloat16_rn(vals[j]);
            ph.h[j] = hh;
            pl.h[j] = __float2bfloat16_rn(vals[j] - __bfloat162float(hh));
        }
        *reinterpret_cast<uint2*>(&g_attn_hi[obase + (size_t)d * HW]) = ph.u;
        *reinterpret_cast<uint2*>(&g_attn_lo[obase + (size_t)d * HW]) = pl.u;
    }
}

// ==========================================================================
// launcher
// ==========================================================================
extern "C" void kernel_launch(void* const* d_in, const int* in_sizes, int n_in,
                              void* d_out, int out_size)
{
    const float* x            = (const float*)d_in[0];
    const float* qkv_w        = (const float*)d_in[1];
    const float* qkv_bn_scale = (const float*)d_in[2];
    const float* qkv_bn_bias  = (const float*)d_in[3];
    const float* agg_dw_w     = (const float*)d_in[4];
    const float* agg_dw_b     = (const float*)d_in[5];
    const float* agg_pw_w     = (const float*)d_in[6];
    const float* agg_pw_b     = (const float*)d_in[7];
    const float* proj_w       = (const float*)d_in[8];
    const float* proj_bn_scale= (const float*)d_in[9];
    const float* proj_bn_bias = (const float*)d_in[10];
    float* out = (float*)d_out;

    __nv_bfloat16 *xh, *xl, *wqh, *wql, *wph, *wpl, *ah, *al;
    cudaGetSymbolAddress((void**)&xh,  g_x_hi);
    cudaGetSymbolAddress((void**)&xl,  g_x_lo);
    cudaGetSymbolAddress((void**)&wqh, g_wqkv_hi);
    cudaGetSymbolAddress((void**)&wql, g_wqkv_lo);
    cudaGetSymbolAddress((void**)&wph, g_wproj_hi);
    cudaGetSymbolAddress((void**)&wpl, g_wproj_lo);
    cudaGetSymbolAddress((void**)&ah,  g_attn_hi);
    cudaGetSymbolAddress((void**)&al,  g_attn_lo);

    (void)cudaFuncSetAttribute(gemm_bf16x3<C3, CIN>,
                               cudaFuncAttributeMaxDynamicSharedMemorySize, SMEM_DYN);
    (void)cudaFuncSetAttribute(gemm_bf16x3<COUT, CCAT>,
                               cudaFuncAttributeMaxDynamicSharedMemorySize, SMEM_DYN);
    (void)cudaFuncSetAttribute(attn_reduce_kernel,
                               cudaFuncAttributeMaxDynamicSharedMemorySize, RSMEM_DYN);

    // 0) fused pre-split of all operands to bf16 hi/lo (one launch)
    {
        to_hilo_all<<<BLK_X + BLK_WQ + BLK_WP, 256>>>(
            (const float4*)x, (const float4*)qkv_w, (const float4*)proj_w);
    }
    // 1) qkv = relu(bn(conv1x1(x)))
    {
        float* gq;
        cudaGetSymbolAddress((void**)&gq, g_qkv);
        dim3 grid(HW / 128, C3 / 128, BATCH);
        gemm_bf16x3<C3, CIN><<<grid, 128, SMEM_DYN>>>(
            wqh, wql, xh, xl, qkv_bn_scale, qkv_bn_bias, gq);
    }
    // 2) agg = pw(dw5x5(qkv))
    {
        dim3 grid(C3, BATCH);
        dw5x5_pw_kernel<<<grid, 256>>>(agg_dw_w, agg_dw_b, agg_pw_w, agg_pw_b);
    }
    // 3a) per-head vk / ksum
    {
        dim3 grid(NHEAD, BATCH);
        attn_reduce_kernel<<<grid, 256, RSMEM_DYN>>>();
    }
    // 3b) apply + normalize (emits bf16 hi/lo)
    {
        dim3 grid(HW / 1024, NHEAD, BATCH);
        attn_apply_kernel<<<grid, 256>>>();
    }
    // 4) out = relu(bn(conv1x1(attn)))
    {
        dim3 grid(HW / 128, COUT / 128, BATCH);
        gemm_bf16x3<COUT, CCAT><<<grid, 128, SMEM_DYN>>>(
            wph, wpl, ah, al, proj_bn_scale, proj_bn_bias, out);
    }
}

// round 17
// speedup vs baseline: 1.4543x; 1.0116x over previous
#include <cuda_runtime.h>
#include <cuda_bf16.h>
#include <mma.h>
#include <cstdint>

using namespace nvcuda;

// ---------------- problem constants ----------------
#define HW     4096      // 64*64
#define IMGW   64
#define BATCH  16
#define CIN    256
#define C3     768
#define CCAT   512
#define COUT   256
#define NHEAD  64
#define ATT_EPS 1e-5f

// ---------------- scratch (device globals; no allocations) ----------------
__device__ float g_qkv [(size_t)BATCH * C3   * HW];
__device__ float g_agg [(size_t)BATCH * C3   * HW];
__device__ float g_vk  [BATCH * NHEAD * 72];

// bf16 hi/lo operand mirrors (error-compensated GEMM inputs)
__device__ __nv_bfloat16 g_x_hi   [(size_t)BATCH * CIN  * HW];
__device__ __nv_bfloat16 g_x_lo   [(size_t)BATCH * CIN  * HW];
__device__ __nv_bfloat16 g_attn_hi[(size_t)BATCH * CCAT * HW];
__device__ __nv_bfloat16 g_attn_lo[(size_t)BATCH * CCAT * HW];
__device__ __nv_bfloat16 g_wqkv_hi[C3 * CIN];
__device__ __nv_bfloat16 g_wqkv_lo[C3 * CIN];
__device__ __nv_bfloat16 g_wproj_hi[COUT * CCAT];
__device__ __nv_bfloat16 g_wproj_lo[COUT * CCAT];

// ---------------- cp.async helpers ----------------
__device__ __forceinline__ void cp_async16(void* smem_dst, const void* gmem_src) {
    uint32_t s = (uint32_t)__cvta_generic_to_shared(smem_dst);
    asm volatile("cp.async.cg.shared.global [%0], [%1], 16;" :: "r"(s), "l"(gmem_src));
}
__device__ __forceinline__ void cp_commit() {
    asm volatile("cp.async.commit_group;");
}
template<int N>
__device__ __forceinline__ void cp_wait() {
    asm volatile("cp.async.wait_group %0;" :: "n"(N));
}

// ==========================================================================
// Fused fp32 -> bf16 hi/lo conversion for x, qkv_w, proj_w (one launch).
// ==========================================================================
#define N4_X   (BATCH * CIN * HW / 4)
#define N4_WQ  (C3 * CIN / 4)
#define N4_WP  (COUT * CCAT / 4)
#define BLK_X  (N4_X  / 256)
#define BLK_WQ (N4_WQ / 256)
#define BLK_WP (N4_WP / 256)

__global__ __launch_bounds__(256)
void to_hilo_all(const float4* __restrict__ x,
                 const float4* __restrict__ wq,
                 const float4* __restrict__ wp)
{
    const float4* src;
    uint2 *hi, *lo;
    int i;
    int blk = blockIdx.x;
    if (blk < BLK_X) {
        src = x;  hi = (uint2*)g_x_hi;    lo = (uint2*)g_x_lo;
        i = blk * 256 + threadIdx.x;
    } else if (blk < BLK_X + BLK_WQ) {
        src = wq; hi = (uint2*)g_wqkv_hi; lo = (uint2*)g_wqkv_lo;
        i = (blk - BLK_X) * 256 + threadIdx.x;
    } else {
        src = wp; hi = (uint2*)g_wproj_hi; lo = (uint2*)g_wproj_lo;
        i = (blk - BLK_X - BLK_WQ) * 256 + threadIdx.x;
    }
    float4 v = src[i];
    float xs[4] = {v.x, v.y, v.z, v.w};
    union { __nv_bfloat16 h[4]; uint2 u; } ph, pl;
    #pragma unroll
    for (int j = 0; j < 4; j++) {
        __nv_bfloat16 hh = __float2bfloat16_rn(xs[j]);
        ph.h[j] = hh;
        pl.h[j] = __float2bfloat16_rn(xs[j] - __bfloat162float(hh));
    }
    hi[i] = ph.u;
    lo[i] = pl.u;
}

// ==========================================================================
// bf16x3 wmma GEMM + BN + ReLU. Block 128Mx128N, BK=32, 128 threads =
// 4 warps of 64x64 (4x4 m16n16k16 frags). 2-stage cp.async, 2 CTAs/SM.
// A-fragment ping-pong (prefetch A(i+1) during i's MMAs); B frags single-set.
//   Out[b,m,n] = relu(scale[m] * sum_k W[m,k] X[b,k,n] + bias[m])
// ==========================================================================
#define LDA 40
#define LDB 136
#define LDC 132

#define OFF_AHI 0
#define OFF_ALO 10240
#define OFF_BHI 20480
#define OFF_BLO 29184
#define STAGE_BYTES 37888
#define SMEM_DYN (2 * STAGE_BYTES)   // 75776 >= 128*132*4 = 67584 epilogue

template<int Mt, int Kt>
__global__ __launch_bounds__(128, 2)
void gemm_bf16x3(const __nv_bfloat16* __restrict__ Wh,
                 const __nv_bfloat16* __restrict__ Wl,
                 const __nv_bfloat16* __restrict__ Xh,
                 const __nv_bfloat16* __restrict__ Xl,
                 const float* __restrict__ scale,
                 const float* __restrict__ bias,
                 float* __restrict__ Out)
{
    extern __shared__ __align__(16) char dynsmem[];

    const int b     = blockIdx.z;
    const int mBase = blockIdx.y * 128;
    const int nBase = blockIdx.x * 128;
    const int tid   = threadIdx.x;
    const int wid   = tid >> 5;
    const int warpM = wid & 1;     // 0..1 (64 rows)
    const int warpN = wid >> 1;    // 0..1 (64 cols)

    const __nv_bfloat16* __restrict__ Xhb = Xh + (size_t)b * Kt * HW;
    const __nv_bfloat16* __restrict__ Xlb = Xl + (size_t)b * Kt * HW;

    auto stage_async = [&](int k0, char* buf) {
        __nv_bfloat16* Ahi = reinterpret_cast<__nv_bfloat16*>(buf + OFF_AHI);
        __nv_bfloat16* Alo = reinterpret_cast<__nv_bfloat16*>(buf + OFF_ALO);
        __nv_bfloat16* Bhi = reinterpret_cast<__nv_bfloat16*>(buf + OFF_BHI);
        __nv_bfloat16* Blo = reinterpret_cast<__nv_bfloat16*>(buf + OFF_BLO);
        #pragma unroll
        for (int t = 0; t < 4; t++) {
            int idx = tid + t * 128;            // 512 uint4
            int ar = idx >> 2, ac = (idx & 3) * 8;
            cp_async16(&Ahi[ar * LDA + ac], &Wh[(size_t)(mBase + ar) * Kt + k0 + ac]);
            cp_async16(&Alo[ar * LDA + ac], &Wl[(size_t)(mBase + ar) * Kt + k0 + ac]);
            int br = idx >> 4, bc = (idx & 15) * 8;
            cp_async16(&Bhi[br * LDB + bc], &Xhb[(size_t)(k0 + br) * HW + nBase + bc]);
            cp_async16(&Blo[br * LDB + bc], &Xlb[(size_t)(k0 + br) * HW + nBase + bc]);
        }
    };

    wmma::fragment<wmma::accumulator, 16, 16, 16, float> acc[4][4];
    #pragma unroll
    for (int i = 0; i < 4; i++)
        #pragma unroll
        for (int j = 0; j < 4; j++) wmma::fill_fragment(acc[i][j], 0.f);

    constexpr int NCHUNK = Kt / 32;
    stage_async(0, dynsmem);
    cp_commit();

    #pragma unroll 1
    for (int chunk = 0; chunk < NCHUNK; chunk++) {
        if (chunk + 1 < NCHUNK) {
            stage_async((chunk + 1) * 32, dynsmem + ((chunk + 1) & 1) * STAGE_BYTES);
            cp_commit();
            cp_wait<1>();
        } else {
            cp_wait<0>();
        }
        __syncthreads();

        char* buf = dynsmem + (chunk & 1) * STAGE_BYTES;
        __nv_bfloat16* Ahi = reinterpret_cast<__nv_bfloat16*>(buf + OFF_AHI);
        __nv_bfloat16* Alo = reinterpret_cast<__nv_bfloat16*>(buf + OFF_ALO);
        __nv_bfloat16* Bhi = reinterpret_cast<__nv_bfloat16*>(buf + OFF_BHI);
        __nv_bfloat16* Blo = reinterpret_cast<__nv_bfloat16*>(buf + OFF_BLO);

        #pragma unroll
        for (int kk = 0; kk < 2; kk++) {
            wmma::fragment<wmma::matrix_b, 16, 16, 16, __nv_bfloat16,
                           wmma::row_major> bfh[4], bfl[4];
            #pragma unroll
            for (int j = 0; j < 4; j++) {
                const int ro = (kk * 16) * LDB + warpN * 64 + j * 16;
                wmma::load_matrix_sync(bfh[j], &Bhi[ro], LDB);
                wmma::load_matrix_sync(bfl[j], &Blo[ro], LDB);
            }
            // A-fragment ping-pong: prefetch A(i+1) during i's MMAs
            wmma::fragment<wmma::matrix_a, 16, 16, 16, __nv_bfloat16,
                           wmma::row_major> afh[2], afl[2];
            {
                const int ro = (warpM * 64) * LDA + kk * 16;
                wmma::load_matrix_sync(afh[0], &Ahi[ro], LDA);
                wmma::load_matrix_sync(afl[0], &Alo[ro], LDA);
            }
            #pragma unroll
            for (int i = 0; i < 4; i++) {
                if (i < 3) {
                    const int ro = (warpM * 64 + (i + 1) * 16) * LDA + kk * 16;
                    wmma::load_matrix_sync(afh[(i + 1) & 1], &Ahi[ro], LDA);
                    wmma::load_matrix_sync(afl[(i + 1) & 1], &Alo[ro], LDA);
                }
                #pragma unroll
                for (int j = 0; j < 4; j++) {
                    wmma::mma_sync(acc[i][j], afl[i & 1], bfh[j], acc[i][j]);
                    wmma::mma_sync(acc[i][j], afh[i & 1], bfl[j], acc[i][j]);
                    wmma::mma_sync(acc[i][j], afh[i & 1], bfh[j], acc[i][j]);
                }
            }
        }
        __syncthreads();
    }

    // ---- single-pass epilogue: Cs[128][LDC] = 67.6KB fits dynsmem, BN+ReLU
    float* Cs = reinterpret_cast<float*>(dynsmem);
    #pragma unroll
    for (int i = 0; i < 4; i++)
        #pragma unroll
        for (int j = 0; j < 4; j++)
            wmma::store_matrix_sync(
                &Cs[(warpM * 64 + i * 16) * LDC + warpN * 64 + j * 16],
                acc[i][j], LDC, wmma::mem_row_major);
    __syncthreads();
    #pragma unroll
    for (int t = 0; t < 32; t++) {
        int idx = tid + t * 128;              // 4096 float4
        int r = idx >> 5, c4 = (idx & 31) * 4;
        int m = mBase + r;
        const float sc = scale[m], bi = bias[m];
        float4 v = *reinterpret_cast<const float4*>(&Cs[r * LDC + c4]);
        v.x = fmaxf(fmaf(v.x, sc, bi), 0.f);
        v.y = fmaxf(fmaf(v.y, sc, bi), 0.f);
        v.z = fmaxf(fmaf(v.z, sc, bi), 0.f);
        v.w = fmaxf(fmaf(v.w, sc, bi), 0.f);
        *reinterpret_cast<float4*>(
            &Out[(size_t)b * Mt * HW + (size_t)m * HW + nBase + c4]) = v;
    }
}

// ==========================================================================
// Fused depthwise 5x5 + per-channel 1x1, smem-tiled with sliding window.
// ==========================================================================
#define TILE_W 68
__global__ __launch_bounds__(256)
void dw5x5_pw_kernel(const float* __restrict__ dw_w,
                     const float* __restrict__ dw_b,
                     const float* __restrict__ pw_w,
                     const float* __restrict__ pw_b)
{
    __shared__ float tile[TILE_W * TILE_W];
    const int c = blockIdx.x;
    const int b = blockIdx.y;
    const int tid = threadIdx.x;

    const float* __restrict__ src = g_qkv + ((size_t)b * C3 + c) * HW;

    for (int idx = tid; idx < TILE_W * TILE_W; idx += 256) {
        int r = idx / TILE_W - 2;
        int cc = idx % TILE_W - 2;
        float v = 0.f;
        if ((unsigned)r < IMGW && (unsigned)cc < IMGW) v = src[r * IMGW + cc];
        tile[idx] = v;
    }

    float wreg[25];
    #pragma unroll
    for (int i = 0; i < 25; i++) wreg[i] = __ldg(&dw_w[c * 25 + i]);
    const float dwb = __ldg(&dw_b[c]);
    const float pww = __ldg(&pw_w[c]);
    const float pwb = __ldg(&pw_b[c]);
    __syncthreads();

    const int row = tid >> 2;
    const int xs  = (tid & 3) * 16;

    float acc[16];
    #pragma unroll
    for (int i = 0; i < 16; i++) acc[i] = 0.f;

    #pragma unroll
    for (int dy = 0; dy < 5; dy++) {
        const float* trow = &tile[(row + dy) * TILE_W + xs];
        float win[20];
        #pragma unroll
        for (int i = 0; i < 20; i++) win[i] = trow[i];
        const float w0 = wreg[dy * 5 + 0], w1 = wreg[dy * 5 + 1],
                    w2 = wreg[dy * 5 + 2], w3 = wreg[dy * 5 + 3],
                    w4 = wreg[dy * 5 + 4];
        #pragma unroll
        for (int i = 0; i < 16; i++) {
            float s = acc[i];
            s = fmaf(win[i + 0], w0, s);
            s = fmaf(win[i + 1], w1, s);
            s = fmaf(win[i + 2], w2, s);
            s = fmaf(win[i + 3], w3, s);
            s = fmaf(win[i + 4], w4, s);
            acc[i] = s;
        }
    }

    float* dst = g_agg + ((size_t)b * C3 + c) * HW + row * IMGW + xs;
    #pragma unroll
    for (int i4 = 0; i4 < 16; i4 += 4) {
        float4 v;
        v.x = fmaf(acc[i4 + 0] + dwb, pww, pwb);
        v.y = fmaf(acc[i4 + 1] + dwb, pww, pwb);
        v.z = fmaf(acc[i4 + 2] + dwb, pww, pwb);
        v.w = fmaf(acc[i4 + 3] + dwb, pww, pwb);
        *reinterpret_cast<float4*>(dst + i4) = v;
    }
}

// ==========================================================================
// Attention phase 1: smem-staged warp-per-d with cp.async double buffer.
// ==========================================================================
#define RCHUNK 512
#define RBUF_FLOATS (16 * RCHUNK)
#define RSMEM_DYN (2 * RBUF_FLOATS * 4)    // 65536 bytes

__global__ __launch_bounds__(256)
void attn_reduce_kernel()
{
    extern __shared__ __align__(16) float rsm[];

    const int head = blockIdx.x;
    const int b    = blockIdx.y;
    const float* __restrict__ src = (head < 32) ? g_qkv : g_agg;
    const int ch0 = (head & 31) * 24;
    const float* __restrict__ base = src + ((size_t)b * C3 + ch0) * HW;

    const int tid  = threadIdx.x;
    const int wid  = tid >> 5;
    const int lane = tid & 31;

    auto stage = [&](int n0, float* buf) {
        #pragma unroll
        for (int t = 0; t < 4; t++) {
            int idx = tid + t * 256;
            int ch  = idx >> 7;
            int pos = (idx & 127) * 4;
            cp_async16(&buf[ch * RCHUNK + pos],
                       &base[(size_t)(8 + ch) * HW + n0 + pos]);
            cp_async16(&buf[8 * RCHUNK + ch * RCHUNK + pos],
                       &base[(size_t)(16 + ch) * HW + n0 + pos]);
        }
    };

    float acc[8];
    #pragma unroll
    for (int e = 0; e < 8; e++) acc[e] = 0.f;
    float ksum[8];
    #pragma unroll
    for (int e = 0; e < 8; e++) ksum[e] = 0.f;

    constexpr int NCH = HW / RCHUNK;
    stage(0, rsm);
    cp_commit();

    #pragma unroll 1
    for (int c = 0; c < NCH; c++) {
        if (c + 1 < NCH) {
            stage((c + 1) * RCHUNK, rsm + ((c + 1) & 1) * RBUF_FLOATS);
            cp_commit();
            cp_wait<1>();
        } else {
            cp_wait<0>();
        }
        __syncthreads();

        const float* ks = rsm + (c & 1) * RBUF_FLOATS;
        const float* vs = ks + 8 * RCHUNK;

        if (wid == 0) {
            #pragma unroll
            for (int i = 0; i < RCHUNK / 32; i++) {
                const int n = lane + 32 * i;
                const float vd = vs[0 * RCHUNK + n];
                #pragma unroll
                for (int e = 0; e < 8; e++) {
                    const float kv = fmaxf(ks[e * RCHUNK + n], 0.f);
                    acc[e]  = fmaf(vd, kv, acc[e]);
                    ksum[e] += kv;
                }
            }
        } else {
            #pragma unroll
            for (int i = 0; i < RCHUNK / 32; i++) {
                const int n = lane + 32 * i;
                const float vd = vs[wid * RCHUNK + n];
                #pragma unroll
                for (int e = 0; e < 8; e++)
                    acc[e] = fmaf(vd, fmaxf(ks[e * RCHUNK + n], 0.f), acc[e]);
            }
        }
        __syncthreads();
    }

    float* dst = &g_vk[((size_t)b * NHEAD + head) * 72];
    #pragma unroll
    for (int e = 0; e < 8; e++) {
        float v = acc[e];
        #pragma unroll
        for (int off = 16; off > 0; off >>= 1)
            v += __shfl_down_sync(0xffffffffu, v, off);
        if (lane == 0) dst[wid * 8 + e] = v;
    }
    if (wid == 0) {
        #pragma unroll
        for (int e = 0; e < 8; e++) {
            float v = ksum[e];
            #pragma unroll
            for (int off = 16; off > 0; off >>= 1)
                v += __shfl_down_sync(0xffffffffu, v, off);
            if (lane == 0) dst[64 + e] = v;
        }
    }
}

// ==========================================================================
// Attention phase 2: apply + normalize; float4 vectorized, packed bf16 out.
// ==========================================================================
__global__ __launch_bounds__(256)
void attn_apply_kernel()
{
    const int head = blockIdx.y;
    const int b    = blockIdx.z;
    const int n    = (blockIdx.x * 256 + threadIdx.x) * 4;

    __shared__ float s[72];
    if (threadIdx.x < 72)
        s[threadIdx.x] = g_vk[((size_t)b * NHEAD + head) * 72 + threadIdx.x];
    __syncthreads();

    const float* __restrict__ src = (head < 32) ? g_qkv : g_agg;
    const int ch0 = (head & 31) * 24;
    const float* __restrict__ base = src + ((size_t)b * C3 + ch0) * HW;

    float4 q[8];
    #pragma unroll
    for (int e = 0; e < 8; e++) {
        float4 t = *reinterpret_cast<const float4*>(&base[(size_t)e * HW + n]);
        q[e].x = fmaxf(t.x, 0.f); q[e].y = fmaxf(t.y, 0.f);
        q[e].z = fmaxf(t.z, 0.f); q[e].w = fmaxf(t.w, 0.f);
    }

    float4 denom = make_float4(ATT_EPS, ATT_EPS, ATT_EPS, ATT_EPS);
    #pragma unroll
    for (int e = 0; e < 8; e++) {
        const float ks = s[64 + e];
        denom.x = fmaf(ks, q[e].x, denom.x);
        denom.y = fmaf(ks, q[e].y, denom.y);
        denom.z = fmaf(ks, q[e].z, denom.z);
        denom.w = fmaf(ks, q[e].w, denom.w);
    }
    const float4 inv = make_float4(1.f / denom.x, 1.f / denom.y,
                                   1.f / denom.z, 1.f / denom.w);

    const size_t obase = ((size_t)b * CCAT + head * 8) * HW + n;
    #pragma unroll
    for (int d = 0; d < 8; d++) {
        float4 o = make_float4(0.f, 0.f, 0.f, 0.f);
        #pragma unroll
        for (int e = 0; e < 8; e++) {
            const float vk = s[d * 8 + e];
            o.x = fmaf(vk, q[e].x, o.x);
            o.y = fmaf(vk, q[e].y, o.y);
            o.z = fmaf(vk, q[e].z, o.z);
            o.w = fmaf(vk, q[e].w, o.w);
        }
        float vals[4] = {o.x * inv.x, o.y * inv.y, o.z * inv.z, o.w * inv.w};
        union { __nv_bfloat16 h[4]; uint2 u; } ph, pl;
        #pragma unroll
        for (int j = 0; j < 4; j++) {
            __nv_bfloat16 hh = __float2bfloat16_rn(vals[j]);
            ph.h[j] = hh;
            pl.h[j] = __float2bfloat16_rn(vals[j] - __bfloat162float(hh));
        }
        *reinterpret_cast<uint2*>(&g_attn_hi[obase + (size_t)d * HW]) = ph.u;
        *reinterpret_cast<uint2*>(&g_attn_lo[obase + (size_t)d * HW]) = pl.u;
    }
}

// ==========================================================================
// launcher
// ==========================================================================
extern "C" void kernel_launch(void* const* d_in, const int* in_sizes, int n_in,
                              void* d_out, int out_size)
{
    const float* x            = (const float*)d_in[0];
    const float* qkv_w        = (const float*)d_in[1];
    const float* qkv_bn_scale = (const float*)d_in[2];
    const float* qkv_bn_bias  = (const float*)d_in[3];
    const float* agg_dw_w     = (const float*)d_in[4];
    const float* agg_dw_b     = (const float*)d_in[5];
    const float* agg_pw_w     = (const float*)d_in[6];
    const float* agg_pw_b     = (const float*)d_in[7];
    const float* proj_w       = (const float*)d_in[8];
    const float* proj_bn_scale= (const float*)d_in[9];
    const float* proj_bn_bias = (const float*)d_in[10];
    float* out = (float*)d_out;

    __nv_bfloat16 *xh, *xl, *wqh, *wql, *wph, *wpl, *ah, *al;
    cudaGetSymbolAddress((void**)&xh,  g_x_hi);
    cudaGetSymbolAddress((void**)&xl,  g_x_lo);
    cudaGetSymbolAddress((void**)&wqh, g_wqkv_hi);
    cudaGetSymbolAddress((void**)&wql, g_wqkv_lo);
    cudaGetSymbolAddress((void**)&wph, g_wproj_hi);
    cudaGetSymbolAddress((void**)&wpl, g_wproj_lo);
    cudaGetSymbolAddress((void**)&ah,  g_attn_hi);
    cudaGetSymbolAddress((void**)&al,  g_attn_lo);

    (void)cudaFuncSetAttribute(gemm_bf16x3<C3, CIN>,
                               cudaFuncAttributeMaxDynamicSharedMemorySize, SMEM_DYN);
    (void)cudaFuncSetAttribute(gemm_bf16x3<COUT, CCAT>,
                               cudaFuncAttributeMaxDynamicSharedMemorySize, SMEM_DYN);
    (void)cudaFuncSetAttribute(attn_reduce_kernel,
                               cudaFuncAttributeMaxDynamicSharedMemorySize, RSMEM_DYN);

    // 0) fused pre-split of all operands to bf16 hi/lo (one launch)
    {
        to_hilo_all<<<BLK_X + BLK_WQ + BLK_WP, 256>>>(
            (const float4*)x, (const float4*)qkv_w, (const float4*)proj_w);
    }
    // 1) qkv = relu(bn(conv1x1(x)))
    {
        float* gq;
        cudaGetSymbolAddress((void**)&gq, g_qkv);
        dim3 grid(HW / 128, C3 / 128, BATCH);
        gemm_bf16x3<C3, CIN><<<grid, 128, SMEM_DYN>>>(
            wqh, wql, xh, xl, qkv_bn_scale, qkv_bn_bias, gq);
    }
    // 2) agg = pw(dw5x5(qkv))
    {
        dim3 grid(C3, BATCH);
        dw5x5_pw_kernel<<<grid, 256>>>(agg_dw_w, agg_dw_b, agg_pw_w, agg_pw_b);
    }
    // 3a) per-head vk / ksum
    {
        dim3 grid(NHEAD, BATCH);
        attn_reduce_kernel<<<grid, 256, RSMEM_DYN>>>();
    }
    // 3b) apply + normalize (emits bf16 hi/lo)
    {
        dim3 grid(HW / 1024, NHEAD, BATCH);
        attn_apply_kernel<<<grid, 256>>>();
    }
    // 4) out = relu(bn(conv1x1(attn)))
    {
        dim3 grid(HW / 128, COUT / 128, BATCH);
        gemm_bf16x3<COUT, CCAT><<<grid, 128, SMEM_DYN>>>(
            wph, wpl, ah, al, proj_bn_scale, proj_bn_bias, out);
    }
}